// round 13
// baseline (speedup 1.0000x reference)
#include <cuda_runtime.h>

#define TDIM 200
#define PDIM 784
#define BDIM 256
#define PSPLIT 16
#define PCHUNK 49     // 784 / 16
#define BTILE 16
#define NUBLK (PSPLIT * (BDIM / BTILE))   // 256 u blocks
#define PI_F 3.14159265358979323846f

// dynamic smem (bytes): s_ri (49*200 packed pairs) 78400 | xv 6272
#define SMEM_BYTES (PCHUNK * TDIM * 8 + PCHUNK * BTILE * 8)

typedef unsigned long long ull;

// Scratch (no allocation allowed)
__device__ __align__(16) float2 g_Dt[TDIM * TDIM];   // [t][f], imag NEGATED, /T
__device__ __align__(16) float2 g_u[PSPLIT][BDIM * TDIM];  // p-split partials

// ---- packed f32x2 helpers ------------------------------------------------
__device__ __forceinline__ void upk2(ull v, float& x, float& y) {
    asm("mov.b64 {%0, %1}, %2;" : "=f"(x), "=f"(y) : "l"(v));
}
__device__ __forceinline__ void fma2(ull& acc, ull a, ull b) {
    asm("fma.rn.f32x2 %0, %1, %2, %0;" : "+l"(acc) : "l"(a), "l"(b));
}

// ---------------------------------------------------------------------------
// K1 (merged): flat grid 456, block 200 threads.
//   blocks [0, 256):   u[b][f] = sum_p x[b][p]v[p] * S[p][f]   (complex GEMM)
//   blocks [256, 456): t = blk-256. Thread f computes c[f] (200-pt DFT *
//                      envelope) INLINE, then writes D^T[t][f] — no separate
//                      launch, no cross-kernel dependency.
// ---------------------------------------------------------------------------
__global__ void __launch_bounds__(TDIM, 2) k_uD(const float* __restrict__ x,
                                                const float* __restrict__ v,
                                                const float* __restrict__ sre,
                                                const float* __restrict__ sim,
                                                const float* __restrict__ wre,
                                                const float* __restrict__ wim,
                                                const float* __restrict__ ere,
                                                const float* __restrict__ eim) {
    extern __shared__ __align__(16) float sm[];
    const int blk = blockIdx.x;
    const int tid = threadIdx.x;

    if (blk >= NUBLK) {
        // ---- D branch: block computes row t of D^T, c[f] inline ----------
        const int t = blk - NUBLK;
        float2* tw   = (float2*)sm;        // floats [0,400)
        float*  wr_s = sm + 400;
        float*  wi_s = sm + 600;
        const int f = tid;
        {
            float ang = (2.0f * PI_F / TDIM) * (float)f;
            float si, co;
            sincosf(ang, &si, &co);
            tw[f] = make_float2(co, si);
            wr_s[f] = wre[f];
            wi_s[f] = wim[f];
        }
        __syncthreads();
        // c[f] = DFT(waveform)[f] * env[f]   (exact twiddle indices)
        float ar = 0.f, ai = 0.f;
        int m = 0;  // (f*tau) mod 200
        for (int tau = 0; tau < TDIM; tau++) {
            float2 w = tw[m];
            m += f; if (m >= TDIM) m -= TDIM;
            float xr = wr_s[tau], xi = wi_s[tau];
            ar += xr * w.x + xi * w.y;   // x * e^{-i ang}
            ai += xi * w.x - xr * w.y;
        }
        float er = ere[f], ei = eim[f];
        float cx = ar * er - ai * ei;
        float cy = ar * ei + ai * er;
        // D^T[t][f] = (Re, -Im) of c[f] * e^{+i 2pi f t/T} / T
        int m2 = (f * t) % TDIM;
        float2 w2 = tw[m2];
        const float inv = 1.0f / TDIM;
        g_Dt[t * TDIM + f] = make_float2((cx * w2.x - cy * w2.y) * inv,
                                         -(cx * w2.y + cy * w2.x) * inv);
        return;
    }

    // ---- u branch (R11 measured-best mainloop, unchanged) ----
    ull*    s_ri = (ull*)sm;                              // [49*200] (re,im)
    float2* xv_s = (float2*)(sm + 2 * PCHUNK * TDIM);     // [49][16] (a,a)

    const int s  = blk >> 4;          // p-split 0..15
    const int b0 = (blk & 15) * BTILE;
    const int p0 = s * PCHUNK;

    // stage S slice interleaved (re,im): row length 200 % 4 == 0, so each
    // float4 stays within one p-row.
    {
        const float4* sr4 = (const float4*)(sre + (size_t)p0 * TDIM);
        const float4* si4 = (const float4*)(sim + (size_t)p0 * TDIM);
        float4* dst = (float4*)s_ri;
        const int N4 = PCHUNK * TDIM / 4;   // 2450
#pragma unroll
        for (int it = 0; it < 13; it++) {
            int i = tid + it * TDIM;
            if (i < N4) {
                float4 r4 = sr4[i];
                float4 i4 = si4[i];
                dst[2 * i + 0] = make_float4(r4.x, i4.x, r4.y, i4.y);
                dst[2 * i + 1] = make_float4(r4.z, i4.z, r4.w, i4.w);
            }
        }
    }
    // stage xv (duplicated (a,a) packs)
#pragma unroll
    for (int it = 0; it < 4; it++) {
        int idx = tid + it * TDIM;
        if (idx < PCHUNK * BTILE) {
            int pp = idx >> 4, j = idx & 15;
            float a = x[(b0 + j) * PDIM + p0 + pp] * v[p0 + pp];
            xv_s[pp * BTILE + j] = make_float2(a, a);
        }
    }
    __syncthreads();

    const int f = tid;
    ull acc[BTILE];   // acc[j] = packed (u_re, u_im) for batch b0+j
#pragma unroll
    for (int j = 0; j < BTILE; j++) acc[j] = 0ull;

    const ulonglong2* xvb = (const ulonglong2*)xv_s;   // 8 per p-row

#pragma unroll
    for (int pp = 0; pp < PCHUNK; pp++) {
        ull bpk = s_ri[pp * TDIM + f];        // LDS.64, direct FFMA2 operand
#pragma unroll
        for (int q = 0; q < 8; q++) {
            ulonglong2 a = xvb[pp * 8 + q];   // LDS.128 broadcast, mov-free
            fma2(acc[2 * q + 0], a.x, bpk);   // batch 2q
            fma2(acc[2 * q + 1], a.y, bpk);   // batch 2q+1
        }
    }
#pragma unroll
    for (int j = 0; j < BTILE; j++) {
        float ur, ui_;
        upk2(acc[j], ur, ui_);
        g_u[s][(b0 + j) * TDIM + f] = make_float2(ur, ui_);
    }
}

// ---------------------------------------------------------------------------
// K2: r[b][t] = Re(sum_f u[b][f]*D[f][t]); chunk-max; 10x10 linear
// grid 128 blocks (full chip), block 200 (t); 16-way partial gather, then
// 2 batches per thread off ONE D-row stream. Mov-free FFMA2 inner loop.
// ---------------------------------------------------------------------------
__global__ void __launch_bounds__(TDIM) k_out(const float* __restrict__ lw,
                                              const float* __restrict__ lb,
                                              float* __restrict__ out) {
    __shared__ __align__(16) float2 u_s[2][TDIM];
    __shared__ float vals[2][TDIM];
    __shared__ float cm[2][10];
    const int t  = threadIdx.x;
    const int b0 = blockIdx.x * 2;

    // gather + reduce the 16 p-split partials of u for both batches
#pragma unroll
    for (int bb = 0; bb < 2; bb++) {
        float2 a = make_float2(0.f, 0.f);
#pragma unroll
        for (int s = 0; s < PSPLIT; s++) {
            float2 p = g_u[s][(b0 + bb) * TDIM + t];
            a.x += p.x; a.y += p.y;
        }
        u_s[bb][t] = a;
    }
    __syncthreads();

    const ulonglong2* dp = (const ulonglong2*)(g_Dt + (size_t)t * TDIM);
    const ulonglong2* u0 = (const ulonglong2*)u_s[0];
    const ulonglong2* u1 = (const ulonglong2*)u_s[1];
    ull a0 = 0, a1 = 0, b0a = 0, b1a = 0;
#pragma unroll 10
    for (int j = 0; j < TDIM / 2; j++) {
        ulonglong2 d  = dp[j];   // .x=(dre,-dim)@2j  .y=@2j+1  (LDG.128)
        ulonglong2 w0 = u0[j];   // .x=(ure,uim)@2j   (LDS.128 broadcast)
        ulonglong2 w1 = u1[j];
        fma2(a0, w0.x, d.x);  fma2(b0a, w0.y, d.y);
        fma2(a1, w1.x, d.x);  fma2(b1a, w1.y, d.y);
    }
    {
        float x0, y0, x1, y1;
        upk2(a0, x0, y0); upk2(b0a, x1, y1);
        float r = (x0 + y0) + (x1 + y1);   // sum(ure*dre - uim*dim)
        vals[0][t] = sqrtf(fmaf(r, r, 1e-20f));
        upk2(a1, x0, y0); upk2(b1a, x1, y1);
        r = (x0 + y0) + (x1 + y1);
        vals[1][t] = sqrtf(fmaf(r, r, 1e-20f));
    }
    __syncthreads();

    if (t < 20) {
        int bb = t / 10, c = t % 10;
        float mx = 0.f;
#pragma unroll
        for (int k = 0; k < 20; k++) mx = fmaxf(mx, vals[bb][c * 20 + k]);
        cm[bb][c] = mx;
    }
    __syncthreads();

    if (t < 20) {
        int bb = t / 10, c = t % 10;
        float o = lb[c];
#pragma unroll
        for (int cc = 0; cc < 10; cc++) o = fmaf(cm[bb][cc], lw[c * 10 + cc], o);
        out[(b0 + bb) * 10 + c] = o;
    }
}

// ---------------------------------------------------------------------------
extern "C" void kernel_launch(void* const* d_in, const int* in_sizes, int n_in,
                              void* d_out, int out_size) {
    const float* x   = (const float*)d_in[0];  // [256, 784]
    const float* v   = (const float*)d_in[1];  // [784]
    const float* sre = (const float*)d_in[2];  // [784, 200]
    const float* sim = (const float*)d_in[3];  // [784, 200]
    const float* ere = (const float*)d_in[4];  // [200]
    const float* eim = (const float*)d_in[5];  // [200]
    const float* wre = (const float*)d_in[6];  // [200]
    const float* wim = (const float*)d_in[7];  // [200]
    const float* lw  = (const float*)d_in[8];  // [10, 10]
    const float* lb  = (const float*)d_in[9];  // [10]
    float* out = (float*)d_out;                // [256, 10] float32

    cudaFuncSetAttribute(k_uD, cudaFuncAttributeMaxDynamicSharedMemorySize,
                         SMEM_BYTES);
    k_uD<<<NUBLK + TDIM, TDIM, SMEM_BYTES>>>(x, v, sre, sim,
                                             wre, wim, ere, eim);
    k_out<<<BDIM / 2, TDIM>>>(lw, lb, out);
}

// round 14
// speedup vs baseline: 1.0124x; 1.0124x over previous
#include <cuda_runtime.h>

#define TDIM 200
#define PDIM 784
#define BDIM 256
#define PSPLIT 16
#define PCHUNK 49     // 784 / 16
#define BTILE 16
#define NUBLK (PSPLIT * (BDIM / BTILE))   // 256 u blocks
#define PI_F 3.14159265358979323846f

// k_uD dynamic smem (bytes): s_ri (49*200 packed pairs) 78400 | xv 6272
#define SMEM_BYTES (PCHUNK * TDIM * 8 + PCHUNK * BTILE * 8)

// k_out f-chunking: 5 chunks of 40 f, D rows padded to 21 ulonglong2
#define FC 40
#define NCH (TDIM / FC)         // 5
#define DROW 21                 // padded row stride (odd -> conflict-free LDS)
#define KOUT_DS_BYTES (TDIM * DROW * 16)             // 67200
#define KOUT_SMEM (KOUT_DS_BYTES + 2 * TDIM * 8 + 2 * TDIM * 4 + 2 * 10 * 4 + 32)

typedef unsigned long long ull;

// Scratch (no allocation allowed)
__device__ __align__(16) float2 g_Dt[TDIM * TDIM];   // [t][f], imag NEGATED, /T
__device__ __align__(16) float2 g_u[PSPLIT][BDIM * TDIM];  // p-split partials

// ---- packed f32x2 helpers ------------------------------------------------
__device__ __forceinline__ void upk2(ull v, float& x, float& y) {
    asm("mov.b64 {%0, %1}, %2;" : "=f"(x), "=f"(y) : "l"(v));
}
__device__ __forceinline__ void fma2(ull& acc, ull a, ull b) {
    asm("fma.rn.f32x2 %0, %1, %2, %0;" : "+l"(acc) : "l"(a), "l"(b));
}

// ---------------------------------------------------------------------------
// K1 (merged): flat grid 456, block 200 threads.
//   blocks [0, 256):   u[b][f] = sum_p x[b][p]v[p] * S[p][f]   (complex GEMM)
//   blocks [256, 456): t = blk-256. Thread f computes c[f] inline, then
//                      writes D^T[t][f].
// ---------------------------------------------------------------------------
__global__ void __launch_bounds__(TDIM, 2) k_uD(const float* __restrict__ x,
                                                const float* __restrict__ v,
                                                const float* __restrict__ sre,
                                                const float* __restrict__ sim,
                                                const float* __restrict__ wre,
                                                const float* __restrict__ wim,
                                                const float* __restrict__ ere,
                                                const float* __restrict__ eim) {
    extern __shared__ __align__(16) float sm[];
    const int blk = blockIdx.x;
    const int tid = threadIdx.x;

    if (blk >= NUBLK) {
        // ---- D branch ----------------------------------------------------
        const int t = blk - NUBLK;
        float2* tw   = (float2*)sm;
        float*  wr_s = sm + 400;
        float*  wi_s = sm + 600;
        const int f = tid;
        {
            float ang = (2.0f * PI_F / TDIM) * (float)f;
            float si, co;
            sincosf(ang, &si, &co);
            tw[f] = make_float2(co, si);
            wr_s[f] = wre[f];
            wi_s[f] = wim[f];
        }
        __syncthreads();
        float ar = 0.f, ai = 0.f;
        int m = 0;  // (f*tau) mod 200 exact
        for (int tau = 0; tau < TDIM; tau++) {
            float2 w = tw[m];
            m += f; if (m >= TDIM) m -= TDIM;
            float xr = wr_s[tau], xi = wi_s[tau];
            ar += xr * w.x + xi * w.y;   // x * e^{-i ang}
            ai += xi * w.x - xr * w.y;
        }
        float er = ere[f], ei = eim[f];
        float cx = ar * er - ai * ei;
        float cy = ar * ei + ai * er;
        int m2 = (f * t) % TDIM;
        float2 w2 = tw[m2];
        const float inv = 1.0f / TDIM;
        g_Dt[t * TDIM + f] = make_float2((cx * w2.x - cy * w2.y) * inv,
                                         -(cx * w2.y + cy * w2.x) * inv);
        return;
    }

    // ---- u branch (R11 measured-best mainloop) ----
    ull*    s_ri = (ull*)sm;                              // [49*200] (re,im)
    float2* xv_s = (float2*)(sm + 2 * PCHUNK * TDIM);     // [49][16] (a,a)

    const int s  = blk >> 4;
    const int b0 = (blk & 15) * BTILE;
    const int p0 = s * PCHUNK;

    {
        const float4* sr4 = (const float4*)(sre + (size_t)p0 * TDIM);
        const float4* si4 = (const float4*)(sim + (size_t)p0 * TDIM);
        float4* dst = (float4*)s_ri;
        const int N4 = PCHUNK * TDIM / 4;   // 2450
#pragma unroll
        for (int it = 0; it < 13; it++) {
            int i = tid + it * TDIM;
            if (i < N4) {
                float4 r4 = sr4[i];
                float4 i4 = si4[i];
                dst[2 * i + 0] = make_float4(r4.x, i4.x, r4.y, i4.y);
                dst[2 * i + 1] = make_float4(r4.z, i4.z, r4.w, i4.w);
            }
        }
    }
#pragma unroll
    for (int it = 0; it < 4; it++) {
        int idx = tid + it * TDIM;
        if (idx < PCHUNK * BTILE) {
            int pp = idx >> 4, j = idx & 15;
            float a = x[(b0 + j) * PDIM + p0 + pp] * v[p0 + pp];
            xv_s[pp * BTILE + j] = make_float2(a, a);
        }
    }
    __syncthreads();

    const int f = tid;
    ull acc[BTILE];
#pragma unroll
    for (int j = 0; j < BTILE; j++) acc[j] = 0ull;

    const ulonglong2* xvb = (const ulonglong2*)xv_s;

#pragma unroll
    for (int pp = 0; pp < PCHUNK; pp++) {
        ull bpk = s_ri[pp * TDIM + f];
#pragma unroll
        for (int q = 0; q < 8; q++) {
            ulonglong2 a = xvb[pp * 8 + q];
            fma2(acc[2 * q + 0], a.x, bpk);
            fma2(acc[2 * q + 1], a.y, bpk);
        }
    }
#pragma unroll
    for (int j = 0; j < BTILE; j++) {
        float ur, ui_;
        upk2(acc[j], ur, ui_);
        g_u[s][(b0 + j) * TDIM + f] = make_float2(ur, ui_);
    }
}

// ---------------------------------------------------------------------------
// K2: r[b][t] = Re(sum_f u[b][f]*D[f][t]); chunk-max; 10x10 linear
// grid 128 blocks, block 200 (t). D^T staged through smem in 5 f-chunks of 40:
// 20 INDEPENDENT coalesced LDG.128/thread per chunk (structural MLP), compute
// reads LDS with padded (conflict-free) rows. u reduced once, read broadcast.
// ---------------------------------------------------------------------------
__global__ void __launch_bounds__(TDIM) k_out(const float* __restrict__ lw,
                                              const float* __restrict__ lb,
                                              float* __restrict__ out) {
    extern __shared__ __align__(16) char smc[];
    ulonglong2* d_s2 = (ulonglong2*)smc;                       // [200][21]
    ull*   u_sr = (ull*)(smc + KOUT_DS_BYTES);                 // [2][200]
    float* vals = (float*)(smc + KOUT_DS_BYTES + 2 * TDIM * 8);// [2][200]
    float* cm   = vals + 2 * TDIM;                             // [2][10]

    const int t  = threadIdx.x;
    const int b0 = blockIdx.x * 2;

    // gather + reduce the 16 p-split partials of u for both batches
    {
        float2* u_f2 = (float2*)u_sr;
#pragma unroll
        for (int bb = 0; bb < 2; bb++) {
            float2 a = make_float2(0.f, 0.f);
#pragma unroll
            for (int s = 0; s < PSPLIT; s++) {
                float2 p = g_u[s][(b0 + bb) * TDIM + t];
                a.x += p.x; a.y += p.y;
            }
            u_f2[bb * TDIM + t] = a;
        }
    }
    __syncthreads();

    const ulonglong2* u0 = (const ulonglong2*)u_sr;            // [100]
    const ulonglong2* u1 = (const ulonglong2*)(u_sr + TDIM);   // [100]
    const ulonglong2* Dg = (const ulonglong2*)g_Dt;            // [200*100]
    ull a0 = 0, a1 = 0, b0a = 0, b1a = 0;

    for (int c = 0; c < NCH; c++) {
        const int f0h = c * (FC / 2);   // 20c: ulonglong2 offset within row
        // cooperative chunk load: 4000 ulonglong2, 20 per thread, independent
#pragma unroll
        for (int it = 0; it < 20; it++) {
            int i2 = t + it * TDIM;
            int row = i2 / 20, k2 = i2 % 20;
            d_s2[row * DROW + k2] = Dg[row * 100 + f0h + k2];
        }
        __syncthreads();
#pragma unroll
        for (int k2 = 0; k2 < 20; k2++) {
            ulonglong2 dd = d_s2[t * DROW + k2];  // (dre,-dim)@f, @f+1
            ulonglong2 w0 = u0[f0h + k2];         // (ure,uim)@f, @f+1
            ulonglong2 w1 = u1[f0h + k2];
            fma2(a0, w0.x, dd.x);  fma2(b0a, w0.y, dd.y);
            fma2(a1, w1.x, dd.x);  fma2(b1a, w1.y, dd.y);
        }
        __syncthreads();
    }
    {
        float x0, y0, x1, y1;
        upk2(a0, x0, y0); upk2(b0a, x1, y1);
        float r = (x0 + y0) + (x1 + y1);   // sum(ure*dre - uim*dim)
        vals[0 * TDIM + t] = sqrtf(fmaf(r, r, 1e-20f));
        upk2(a1, x0, y0); upk2(b1a, x1, y1);
        r = (x0 + y0) + (x1 + y1);
        vals[1 * TDIM + t] = sqrtf(fmaf(r, r, 1e-20f));
    }
    __syncthreads();

    if (t < 20) {
        int bb = t / 10, cc = t % 10;
        float mx = 0.f;
#pragma unroll
        for (int k = 0; k < 20; k++) mx = fmaxf(mx, vals[bb * TDIM + cc * 20 + k]);
        cm[bb * 10 + cc] = mx;
    }
    __syncthreads();

    if (t < 20) {
        int bb = t / 10, cc = t % 10;
        float o = lb[cc];
#pragma unroll
        for (int c2 = 0; c2 < 10; c2++)
            o = fmaf(cm[bb * 10 + c2], lw[cc * 10 + c2], o);
        out[(b0 + bb) * 10 + cc] = o;
    }
}

// ---------------------------------------------------------------------------
extern "C" void kernel_launch(void* const* d_in, const int* in_sizes, int n_in,
                              void* d_out, int out_size) {
    const float* x   = (const float*)d_in[0];  // [256, 784]
    const float* v   = (const float*)d_in[1];  // [784]
    const float* sre = (const float*)d_in[2];  // [784, 200]
    const float* sim = (const float*)d_in[3];  // [784, 200]
    const float* ere = (const float*)d_in[4];  // [200]
    const float* eim = (const float*)d_in[5];  // [200]
    const float* wre = (const float*)d_in[6];  // [200]
    const float* wim = (const float*)d_in[7];  // [200]
    const float* lw  = (const float*)d_in[8];  // [10, 10]
    const float* lb  = (const float*)d_in[9];  // [10]
    float* out = (float*)d_out;                // [256, 10] float32

    cudaFuncSetAttribute(k_uD, cudaFuncAttributeMaxDynamicSharedMemorySize,
                         SMEM_BYTES);
    cudaFuncSetAttribute(k_out, cudaFuncAttributeMaxDynamicSharedMemorySize,
                         KOUT_SMEM);
    k_uD<<<NUBLK + TDIM, TDIM, SMEM_BYTES>>>(x, v, sre, sim,
                                             wre, wim, ere, eim);
    k_out<<<BDIM / 2, TDIM, KOUT_SMEM>>>(lw, lb, out);
}

// round 15
// speedup vs baseline: 1.2421x; 1.2269x over previous
#include <cuda_runtime.h>

#define TDIM 200
#define PDIM 784
#define BDIM 256
#define PSPLIT 16
#define PCHUNK 49     // 784 / 16
#define BTILE 16
#define NUBLK (PSPLIT * (BDIM / BTILE))   // 256 u blocks
#define PI_F 3.14159265358979323846f

// k_uD dynamic smem (bytes): s_ri (49*200 packed pairs) 78400 | xv 6272
#define SMEM_BYTES (PCHUNK * TDIM * 8 + PCHUNK * BTILE * 8)

typedef unsigned long long ull;

// Scratch (no allocation allowed)
__device__ __align__(16) float2 g_D[TDIM * TDIM];    // [f][t], imag NEGATED, /T
__device__ __align__(16) float2 g_u[PSPLIT][BDIM * TDIM];  // p-split partials

// ---- packed f32x2 helpers ------------------------------------------------
__device__ __forceinline__ void upk2(ull v, float& x, float& y) {
    asm("mov.b64 {%0, %1}, %2;" : "=f"(x), "=f"(y) : "l"(v));
}
__device__ __forceinline__ void fma2(ull& acc, ull a, ull b) {
    asm("fma.rn.f32x2 %0, %1, %2, %0;" : "+l"(acc) : "l"(a), "l"(b));
}

// ---------------------------------------------------------------------------
// K1 (merged): flat grid 456, block 200 threads.
//   blocks [0, 256):   u[b][f] = sum_p x[b][p]v[p] * S[p][f]   (complex GEMM)
//   blocks [256, 456): f = blk-256. Block computes c[f] by TREE REDUCTION,
//                      then thread t writes D[f][t] — fully COALESCED rows.
// ---------------------------------------------------------------------------
__global__ void __launch_bounds__(TDIM, 2) k_uD(const float* __restrict__ x,
                                                const float* __restrict__ v,
                                                const float* __restrict__ sre,
                                                const float* __restrict__ sim,
                                                const float* __restrict__ wre,
                                                const float* __restrict__ wim,
                                                const float* __restrict__ ere,
                                                const float* __restrict__ eim) {
    extern __shared__ __align__(16) float sm[];
    const int blk = blockIdx.x;
    const int tid = threadIdx.x;

    if (blk >= NUBLK) {
        // ---- D branch: block f; c[f] via reduction; coalesced row write --
        const int f = blk - NUBLK;
        float* rr = sm;            // [200]
        float* ri = sm + 256;      // [200]
        float2* c_sh = (float2*)(sm + 512);
        const int t = tid;         // doubles as tau for the reduction
        const int m = (f * t) % TDIM;               // exact twiddle index
        float ang = (2.0f * PI_F / TDIM) * (float)m;
        float si, co;
        sincosf(ang, &si, &co);
        {
            float xr = wre[t], xi = wim[t];
            rr[t] = xr * co + xi * si;   // Re(w[tau] * e^{-i ang})
            ri[t] = xi * co - xr * si;
        }
        __syncthreads();
        if (t < 100) { rr[t] += rr[t + 100]; ri[t] += ri[t + 100]; }
        __syncthreads();
        if (t < 50)  { rr[t] += rr[t + 50];  ri[t] += ri[t + 50]; }
        __syncthreads();
        if (t < 25)  { rr[t] += rr[t + 25];  ri[t] += ri[t + 25]; }
        __syncthreads();
        if (t < 32) {
            float vr = (t < 25) ? rr[t] : 0.f;
            float vi = (t < 25) ? ri[t] : 0.f;
#pragma unroll
            for (int off = 16; off; off >>= 1) {
                vr += __shfl_down_sync(0xffffffffu, vr, off);
                vi += __shfl_down_sync(0xffffffffu, vi, off);
            }
            if (t == 0) {
                float er = ere[f], ei = eim[f];
                *c_sh = make_float2(vr * er - vi * ei, vr * ei + vi * er);
            }
        }
        __syncthreads();
        float2 c = *c_sh;
        // D[f][t] = (Re, -Im) of c[f] * e^{+i ang} / T   (same sincos!)
        const float inv = 1.0f / TDIM;
        g_D[f * TDIM + t] = make_float2((c.x * co - c.y * si) * inv,
                                        -(c.x * si + c.y * co) * inv);
        return;
    }

    // ---- u branch (R11 measured-best mainloop, unchanged) ----
    ull*    s_ri = (ull*)sm;                              // [49*200] (re,im)
    float2* xv_s = (float2*)(sm + 2 * PCHUNK * TDIM);     // [49][16] (a,a)

    const int s  = blk >> 4;
    const int b0 = (blk & 15) * BTILE;
    const int p0 = s * PCHUNK;

    {
        const float4* sr4 = (const float4*)(sre + (size_t)p0 * TDIM);
        const float4* si4 = (const float4*)(sim + (size_t)p0 * TDIM);
        float4* dst = (float4*)s_ri;
        const int N4 = PCHUNK * TDIM / 4;   // 2450
#pragma unroll
        for (int it = 0; it < 13; it++) {
            int i = tid + it * TDIM;
            if (i < N4) {
                float4 r4 = sr4[i];
                float4 i4 = si4[i];
                dst[2 * i + 0] = make_float4(r4.x, i4.x, r4.y, i4.y);
                dst[2 * i + 1] = make_float4(r4.z, i4.z, r4.w, i4.w);
            }
        }
    }
#pragma unroll
    for (int it = 0; it < 4; it++) {
        int idx = tid + it * TDIM;
        if (idx < PCHUNK * BTILE) {
            int pp = idx >> 4, j = idx & 15;
            float a = x[(b0 + j) * PDIM + p0 + pp] * v[p0 + pp];
            xv_s[pp * BTILE + j] = make_float2(a, a);
        }
    }
    __syncthreads();

    const int f = tid;
    ull acc[BTILE];
#pragma unroll
    for (int j = 0; j < BTILE; j++) acc[j] = 0ull;

    const ulonglong2* xvb = (const ulonglong2*)xv_s;

#pragma unroll
    for (int pp = 0; pp < PCHUNK; pp++) {
        ull bpk = s_ri[pp * TDIM + f];
#pragma unroll
        for (int q = 0; q < 8; q++) {
            ulonglong2 a = xvb[pp * 8 + q];
            fma2(acc[2 * q + 0], a.x, bpk);
            fma2(acc[2 * q + 1], a.y, bpk);
        }
    }
#pragma unroll
    for (int j = 0; j < BTILE; j++) {
        float ur, ui_;
        upk2(acc[j], ur, ui_);
        g_u[s][(b0 + j) * TDIM + f] = make_float2(ur, ui_);
    }
}

// ---------------------------------------------------------------------------
// K2: r[b][t] = Re(sum_f u[b][f]*D[f][t]); chunk-max; 10x10 linear
// grid 128, block 200 (t), 2 batches/thread. D[f][t] layout: lanes read
// CONSECUTIVE addresses (2 lines/warp-LDG). G=8 explicit prefetch pipeline
// (the R7-proven structure) keeps 8 independent LDG.64 in flight. u[f] is
// an LDS.64 broadcast. All FFMA2 operands mov-free.
// ---------------------------------------------------------------------------
__global__ void __launch_bounds__(TDIM) k_out(const float* __restrict__ lw,
                                              const float* __restrict__ lb,
                                              float* __restrict__ out) {
    __shared__ __align__(16) float2 u0f[TDIM], u1f[TDIM];
    __shared__ float vals[2][TDIM];
    __shared__ float cm[2][10];
    const int t  = threadIdx.x;
    const int b0 = blockIdx.x * 2;

    // gather + reduce the 16 p-split partials of u for both batches
    {
        float2 a0 = make_float2(0.f, 0.f), a1 = make_float2(0.f, 0.f);
#pragma unroll
        for (int s = 0; s < PSPLIT; s++) {
            float2 p0 = g_u[s][(b0 + 0) * TDIM + t];
            float2 p1 = g_u[s][(b0 + 1) * TDIM + t];
            a0.x += p0.x; a0.y += p0.y;
            a1.x += p1.x; a1.y += p1.y;
        }
        u0f[t] = a0;
        u1f[t] = a1;
    }
    __syncthreads();

    const ull* Dg  = (const ull*)g_D;     // packed (dre, -dim) at [f*200 + t]
    const ull* u0s = (const ull*)u0f;
    const ull* u1s = (const ull*)u1f;

    ull a0a = 0, a0b = 0, a1a = 0, a1b = 0;
    ull cur[8], nxt[8];
#pragma unroll
    for (int k = 0; k < 8; k++) cur[k] = Dg[k * TDIM + t];   // f = 0..7

    for (int g = 0; g < 25; g++) {
        if (g < 24) {
            const int fb = (g + 1) * 8;
#pragma unroll
            for (int k = 0; k < 8; k++) nxt[k] = Dg[(fb + k) * TDIM + t];
        }
        const int fb = g * 8;
#pragma unroll
        for (int k = 0; k < 8; k++) {
            ull u0 = u0s[fb + k];          // LDS.64 broadcast
            ull u1 = u1s[fb + k];
            if (k & 1) { fma2(a0b, u0, cur[k]); fma2(a1b, u1, cur[k]); }
            else       { fma2(a0a, u0, cur[k]); fma2(a1a, u1, cur[k]); }
        }
#pragma unroll
        for (int k = 0; k < 8; k++) cur[k] = nxt[k];
    }
    {
        float x0, y0, x1, y1;
        upk2(a0a, x0, y0); upk2(a0b, x1, y1);
        float r = (x0 + y0) + (x1 + y1);   // sum(ure*dre - uim*dim)
        vals[0][t] = sqrtf(fmaf(r, r, 1e-20f));
        upk2(a1a, x0, y0); upk2(a1b, x1, y1);
        r = (x0 + y0) + (x1 + y1);
        vals[1][t] = sqrtf(fmaf(r, r, 1e-20f));
    }
    __syncthreads();

    if (t < 20) {
        int bb = t / 10, cc = t % 10;
        float mx = 0.f;
#pragma unroll
        for (int k = 0; k < 20; k++) mx = fmaxf(mx, vals[bb][cc * 20 + k]);
        cm[bb][cc] = mx;
    }
    __syncthreads();

    if (t < 20) {
        int bb = t / 10, cc = t % 10;
        float o = lb[cc];
#pragma unroll
        for (int c2 = 0; c2 < 10; c2++)
            o = fmaf(cm[bb][c2], lw[cc * 10 + c2], o);
        out[(b0 + bb) * 10 + cc] = o;
    }
}

// ---------------------------------------------------------------------------
extern "C" void kernel_launch(void* const* d_in, const int* in_sizes, int n_in,
                              void* d_out, int out_size) {
    const float* x   = (const float*)d_in[0];  // [256, 784]
    const float* v   = (const float*)d_in[1];  // [784]
    const float* sre = (const float*)d_in[2];  // [784, 200]
    const float* sim = (const float*)d_in[3];  // [784, 200]
    const float* ere = (const float*)d_in[4];  // [200]
    const float* eim = (const float*)d_in[5];  // [200]
    const float* wre = (const float*)d_in[6];  // [200]
    const float* wim = (const float*)d_in[7];  // [200]
    const float* lw  = (const float*)d_in[8];  // [10, 10]
    const float* lb  = (const float*)d_in[9];  // [10]
    float* out = (float*)d_out;                // [256, 10] float32

    cudaFuncSetAttribute(k_uD, cudaFuncAttributeMaxDynamicSharedMemorySize,
                         SMEM_BYTES);
    k_uD<<<NUBLK + TDIM, TDIM, SMEM_BYTES>>>(x, v, sre, sim,
                                             wre, wim, ere, eim);
    k_out<<<BDIM / 2, TDIM>>>(lw, lb, out);
}

// round 16
// speedup vs baseline: 1.6214x; 1.3053x over previous
#include <cuda_runtime.h>

#define TDIM 200
#define PDIM 784
#define BDIM 256
#define PSPLIT 16
#define PCHUNK 49     // 784 / 16
#define BTILE 16
#define NUBLK (PSPLIT * (BDIM / BTILE))   // 256 u blocks
#define PI_F 3.14159265358979323846f

// k_uD dynamic smem (bytes): s_ri (49*200 packed pairs) 78400 | xv 6272
#define SMEM_BYTES (PCHUNK * TDIM * 8 + PCHUNK * BTILE * 8)

typedef unsigned long long ull;

// Scratch (no allocation allowed)
__device__ __align__(16) float2 g_D[TDIM * TDIM];    // [f][t], imag NEGATED, /T
__device__ __align__(16) float2 g_u[PSPLIT][BDIM * TDIM];  // p-split partials

// ---- packed f32x2 helpers ------------------------------------------------
__device__ __forceinline__ void upk2(ull v, float& x, float& y) {
    asm("mov.b64 {%0, %1}, %2;" : "=f"(x), "=f"(y) : "l"(v));
}
__device__ __forceinline__ void fma2(ull& acc, ull a, ull b) {
    asm("fma.rn.f32x2 %0, %1, %2, %0;" : "+l"(acc) : "l"(a), "l"(b));
}

// ---------------------------------------------------------------------------
// K1 (merged): flat grid 456, block 200 threads.
//   blocks [0, 256):   u[b][f] = sum_p x[b][p]v[p] * S[p][f]   (complex GEMM)
//   blocks [256, 456): f = blk-256. Block computes c[f] by tree reduction,
//                      then thread t writes D[f][t] — fully coalesced rows.
// ---------------------------------------------------------------------------
__global__ void __launch_bounds__(TDIM, 2) k_uD(const float* __restrict__ x,
                                                const float* __restrict__ v,
                                                const float* __restrict__ sre,
                                                const float* __restrict__ sim,
                                                const float* __restrict__ wre,
                                                const float* __restrict__ wim,
                                                const float* __restrict__ ere,
                                                const float* __restrict__ eim) {
    extern __shared__ __align__(16) float sm[];
    const int blk = blockIdx.x;
    const int tid = threadIdx.x;

    if (blk >= NUBLK) {
        // ---- D branch: block f; c[f] via reduction; coalesced row write --
        const int f = blk - NUBLK;
        float* rr = sm;            // [200]
        float* ri = sm + 256;      // [200]
        float2* c_sh = (float2*)(sm + 512);
        const int t = tid;         // doubles as tau for the reduction
        const int m = (f * t) % TDIM;               // exact twiddle index
        float ang = (2.0f * PI_F / TDIM) * (float)m;
        float si, co;
        sincosf(ang, &si, &co);
        {
            float xr = wre[t], xi = wim[t];
            rr[t] = xr * co + xi * si;   // Re(w[tau] * e^{-i ang})
            ri[t] = xi * co - xr * si;
        }
        __syncthreads();
        if (t < 100) { rr[t] += rr[t + 100]; ri[t] += ri[t + 100]; }
        __syncthreads();
        if (t < 50)  { rr[t] += rr[t + 50];  ri[t] += ri[t + 50]; }
        __syncthreads();
        if (t < 25)  { rr[t] += rr[t + 25];  ri[t] += ri[t + 25]; }
        __syncthreads();
        if (t < 32) {
            float vr = (t < 25) ? rr[t] : 0.f;
            float vi = (t < 25) ? ri[t] : 0.f;
#pragma unroll
            for (int off = 16; off; off >>= 1) {
                vr += __shfl_down_sync(0xffffffffu, vr, off);
                vi += __shfl_down_sync(0xffffffffu, vi, off);
            }
            if (t == 0) {
                float er = ere[f], ei = eim[f];
                *c_sh = make_float2(vr * er - vi * ei, vr * ei + vi * er);
            }
        }
        __syncthreads();
        float2 c = *c_sh;
        // D[f][t] = (Re, -Im) of c[f] * e^{+i ang} / T   (same sincos!)
        const float inv = 1.0f / TDIM;
        g_D[f * TDIM + t] = make_float2((c.x * co - c.y * si) * inv,
                                        -(c.x * si + c.y * co) * inv);
        return;
    }

    // ---- u branch (R11 measured-best mainloop, unchanged) ----
    ull*    s_ri = (ull*)sm;                              // [49*200] (re,im)
    float2* xv_s = (float2*)(sm + 2 * PCHUNK * TDIM);     // [49][16] (a,a)

    const int s  = blk >> 4;
    const int b0 = (blk & 15) * BTILE;
    const int p0 = s * PCHUNK;

    {
        const float4* sr4 = (const float4*)(sre + (size_t)p0 * TDIM);
        const float4* si4 = (const float4*)(sim + (size_t)p0 * TDIM);
        float4* dst = (float4*)s_ri;
        const int N4 = PCHUNK * TDIM / 4;   // 2450
#pragma unroll
        for (int it = 0; it < 13; it++) {
            int i = tid + it * TDIM;
            if (i < N4) {
                float4 r4 = sr4[i];
                float4 i4 = si4[i];
                dst[2 * i + 0] = make_float4(r4.x, i4.x, r4.y, i4.y);
                dst[2 * i + 1] = make_float4(r4.z, i4.z, r4.w, i4.w);
            }
        }
    }
#pragma unroll
    for (int it = 0; it < 4; it++) {
        int idx = tid + it * TDIM;
        if (idx < PCHUNK * BTILE) {
            int pp = idx >> 4, j = idx & 15;
            float a = x[(b0 + j) * PDIM + p0 + pp] * v[p0 + pp];
            xv_s[pp * BTILE + j] = make_float2(a, a);
        }
    }
    __syncthreads();

    const int f = tid;
    ull acc[BTILE];
#pragma unroll
    for (int j = 0; j < BTILE; j++) acc[j] = 0ull;

    const ulonglong2* xvb = (const ulonglong2*)xv_s;

#pragma unroll
    for (int pp = 0; pp < PCHUNK; pp++) {
        ull bpk = s_ri[pp * TDIM + f];
#pragma unroll
        for (int q = 0; q < 8; q++) {
            ulonglong2 a = xvb[pp * 8 + q];
            fma2(acc[2 * q + 0], a.x, bpk);
            fma2(acc[2 * q + 1], a.y, bpk);
        }
    }
#pragma unroll
    for (int j = 0; j < BTILE; j++) {
        float ur, ui_;
        upk2(acc[j], ur, ui_);
        g_u[s][(b0 + j) * TDIM + f] = make_float2(ur, ui_);
    }
}

// ---------------------------------------------------------------------------
// K2: r[b][t] = Re(sum_f u[b][f]*D[f][t]); chunk-max; 10x10 linear
// grid 128, block (200, 2) = 400 threads. ty-half covers f in [100*ty,
// 100*ty+100) for BOTH batches (disjoint D rows -> no redundant traffic),
// then cross-ty smem reduce. 10-deep LDG.64 prefetch pipeline per thread.
// ---------------------------------------------------------------------------
__global__ void __launch_bounds__(2 * TDIM) k_out(const float* __restrict__ lw,
                                                  const float* __restrict__ lb,
                                                  float* __restrict__ out) {
    __shared__ __align__(16) ull u_sh[2][TDIM];    // [batch][f] packed (re,im)
    __shared__ float part[2][2][TDIM];             // [ty][batch][t]
    __shared__ float vals[2][TDIM];
    __shared__ float cm[2][10];
    const int t  = threadIdx.x;
    const int ty = threadIdx.y;
    const int b0 = blockIdx.x * 2;

    // gather + reduce 16 p-split partials: thread (t,ty) does batch b0+ty
    {
        float2 a = make_float2(0.f, 0.f);
#pragma unroll
        for (int s = 0; s < PSPLIT; s++) {
            float2 p = g_u[s][(b0 + ty) * TDIM + t];
            a.x += p.x; a.y += p.y;
        }
        ((float2*)u_sh[ty])[t] = a;
    }
    __syncthreads();

    const ull* Dg  = (const ull*)g_D;     // packed (dre, -dim) at [f*200 + t]
    const ull* u0s = u_sh[0];
    const ull* u1s = u_sh[1];
    const int f0 = ty * 100;

    ull a0a = 0, a0b = 0, a1a = 0, a1b = 0;
    ull cur[10], nxt[10];
#pragma unroll
    for (int k = 0; k < 10; k++) cur[k] = Dg[(f0 + k) * TDIM + t];

    for (int g = 0; g < 10; g++) {
        if (g < 9) {
            const int fb = f0 + (g + 1) * 10;
#pragma unroll
            for (int k = 0; k < 10; k++) nxt[k] = Dg[(fb + k) * TDIM + t];
        }
        const int fb = f0 + g * 10;
#pragma unroll
        for (int k = 0; k < 10; k++) {
            ull uu0 = u0s[fb + k];         // LDS.64 broadcast
            ull uu1 = u1s[fb + k];
            if (k & 1) { fma2(a0b, uu0, cur[k]); fma2(a1b, uu1, cur[k]); }
            else       { fma2(a0a, uu0, cur[k]); fma2(a1a, uu1, cur[k]); }
        }
#pragma unroll
        for (int k = 0; k < 10; k++) cur[k] = nxt[k];
    }
    {
        float x0, y0, x1, y1;
        upk2(a0a, x0, y0); upk2(a0b, x1, y1);
        part[ty][0][t] = (x0 + y0) + (x1 + y1);   // partial sum(ure*dre - uim*dim)
        upk2(a1a, x0, y0); upk2(a1b, x1, y1);
        part[ty][1][t] = (x0 + y0) + (x1 + y1);
    }
    __syncthreads();

    if (ty == 0) {
        float r0 = part[0][0][t] + part[1][0][t];
        float r1 = part[0][1][t] + part[1][1][t];
        vals[0][t] = sqrtf(fmaf(r0, r0, 1e-20f));
        vals[1][t] = sqrtf(fmaf(r1, r1, 1e-20f));
    }
    __syncthreads();

    if (ty == 0 && t < 20) {
        int bb = t / 10, cc = t % 10;
        float mx = 0.f;
#pragma unroll
        for (int k = 0; k < 20; k++) mx = fmaxf(mx, vals[bb][cc * 20 + k]);
        cm[bb][cc] = mx;
    }
    __syncthreads();

    if (ty == 0 && t < 20) {
        int bb = t / 10, cc = t % 10;
        float o = lb[cc];
#pragma unroll
        for (int c2 = 0; c2 < 10; c2++)
            o = fmaf(cm[bb][c2], lw[cc * 10 + c2], o);
        out[(b0 + bb) * 10 + cc] = o;
    }
}

// ---------------------------------------------------------------------------
extern "C" void kernel_launch(void* const* d_in, const int* in_sizes, int n_in,
                              void* d_out, int out_size) {
    const float* x   = (const float*)d_in[0];  // [256, 784]
    const float* v   = (const float*)d_in[1];  // [784]
    const float* sre = (const float*)d_in[2];  // [784, 200]
    const float* sim = (const float*)d_in[3];  // [784, 200]
    const float* ere = (const float*)d_in[4];  // [200]
    const float* eim = (const float*)d_in[5];  // [200]
    const float* wre = (const float*)d_in[6];  // [200]
    const float* wim = (const float*)d_in[7];  // [200]
    const float* lw  = (const float*)d_in[8];  // [10, 10]
    const float* lb  = (const float*)d_in[9];  // [10]
    float* out = (float*)d_out;                // [256, 10] float32

    cudaFuncSetAttribute(k_uD, cudaFuncAttributeMaxDynamicSharedMemorySize,
                         SMEM_BYTES);
    k_uD<<<NUBLK + TDIM, TDIM, SMEM_BYTES>>>(x, v, sre, sim,
                                             wre, wim, ere, eim);
    k_out<<<BDIM / 2, dim3(TDIM, 2)>>>(lw, lb, out);
}